// round 7
// baseline (speedup 1.0000x reference)
#include <cuda_runtime.h>
#include <math.h>

#define B 64
#define T 256
#define D 512
#define G4 2048
#define M_ROWS (B * T)   // 16384
#define DIN2 1024

typedef unsigned long long ull;

// ---------------- f32x2 helpers ----------------
__device__ __forceinline__ void fma2(ull &d, ull a, ull b) {
    asm("fma.rn.f32x2 %0, %1, %2, %0;" : "+l"(d) : "l"(a), "l"(b));
}
__device__ __forceinline__ ull dup2(float v) {
    ull r; unsigned u = __float_as_uint(v);
    asm("mov.b64 %0, {%1, %1};" : "=l"(r) : "r"(u));
    return r;
}
__device__ __forceinline__ float2 unpk(ull v) {
    float2 f;
    asm("mov.b64 {%0, %1}, %2;" : "=f"(f.x), "=f"(f.y) : "l"(v));
    return f;
}

// ---------------- release/acquire barrier primitives ----------------
__device__ __forceinline__ void red_release_add(unsigned* p, unsigned v) {
    asm volatile("red.release.gpu.global.add.u32 [%0], %1;"
                 :: "l"(p), "r"(v) : "memory");
}
__device__ __forceinline__ unsigned ld_acquire(const unsigned* p) {
    unsigned v;
    asm volatile("ld.acquire.gpu.global.u32 %0, [%1];"
                 : "=r"(v) : "l"(p) : "memory");
    return v;
}

// ---------------- device scratch ----------------
__device__ float g_xz_f[(size_t)M_ROWS * G4];
__device__ float g_xz_b[(size_t)M_ROWS * G4];
__device__ float g_y1[(size_t)M_ROWS * DIN2];
__device__ float g_h[2][2 * B * D];
__device__ float g_c[2 * B * D];
__device__ unsigned char g_mask[M_ROWS];
// monotonic arrival counters, padded to 128B per counter
__device__ unsigned g_cta_arr[2][64][32];   // [dir][cta][pad]
__device__ unsigned g_cnt[2][32];           // [dir][pad]

// ---------------- fused: mask + zero h + barrier reset ----------------
__global__ void maskinit_kernel(const float* __restrict__ X) {
    int tid = threadIdx.x;
    int gidx = blockIdx.x * 128 + tid;
    if (gidx < 2 * 2 * B * D) ((float*)g_h)[gidx] = 0.0f;
    if (gidx < 2 * 64 * 32) ((unsigned*)g_cta_arr)[gidx] = 0u;
    if (gidx < 2 * 32) ((unsigned*)g_cnt)[gidx] = 0u;
    int row = blockIdx.x * 4 + (tid >> 5);
    int lane = tid & 31;
    const float* p = X + (size_t)row * D;
    int any = 0;
    for (int k = lane; k < D; k += 32) any |= (p[k] != 0.0f);
    any = __any_sync(0xffffffffu, any);
    if (lane == 0) g_mask[row] = (unsigned char)any;
}

// ---------------- GEMM: C[M,2048] = A[M,K] @ W[K,2048] + bias ----------------
__global__ void __launch_bounds__(256, 2) gemm_bias_kernel(
    const float* __restrict__ Aext, int a_is_y1,
    const float* __restrict__ W, const float* __restrict__ bias,
    int c_sel, int K)
{
    const float* A = a_is_y1 ? g_y1 : Aext;
    float* C = c_sel ? g_xz_b : g_xz_f;

    __shared__ float As[2][16 * 128];
    __shared__ float Bs[2][16 * 128];

    int tid = threadIdx.x;
    int m0 = blockIdx.y << 7, n0 = blockIdx.x << 7;
    int warp = tid >> 5, lane = tid & 31;
    int wm = (warp & 3) << 5, wn = (warp >> 2) << 6;
    int lm = (lane >> 3) << 2, ln = (lane & 7) << 2;
    int am = tid & 127, akg = tid >> 7;
    int bn4 = tid & 31, bk0 = tid >> 5;

    ull acc[8][4];
#pragma unroll
    for (int r = 0; r < 8; r++)
#pragma unroll
        for (int s = 0; s < 4; s++) acc[r][s] = 0ULL;

    float4 aR[2], bR[2];
    const size_t arow = (size_t)(m0 + am) * K;

#define LDG_TILE(k0)                                                          \
    aR[0] = *(const float4*)&A[arow + (k0) + (akg << 2)];                     \
    aR[1] = *(const float4*)&A[arow + (k0) + ((akg + 2) << 2)];               \
    bR[0] = *(const float4*)&W[(size_t)((k0) + bk0) * G4 + n0 + (bn4 << 2)];  \
    bR[1] = *(const float4*)&W[(size_t)((k0) + bk0 + 8) * G4 + n0 + (bn4 << 2)];

#define STS_TILE(buf)                                                         \
    {                                                                         \
        float* Ad = As[buf]; float* Bd = Bs[buf];                             \
        Ad[((akg << 2) + 0) * 128 + am] = aR[0].x;                            \
        Ad[((akg << 2) + 1) * 128 + am] = aR[0].y;                            \
        Ad[((akg << 2) + 2) * 128 + am] = aR[0].z;                            \
        Ad[((akg << 2) + 3) * 128 + am] = aR[0].w;                            \
        Ad[(((akg + 2) << 2) + 0) * 128 + am] = aR[1].x;                      \
        Ad[(((akg + 2) << 2) + 1) * 128 + am] = aR[1].y;                      \
        Ad[(((akg + 2) << 2) + 2) * 128 + am] = aR[1].z;                      \
        Ad[(((akg + 2) << 2) + 3) * 128 + am] = aR[1].w;                      \
        *(float4*)&Bd[bk0 * 128 + (bn4 << 2)] = bR[0];                        \
        *(float4*)&Bd[(bk0 + 8) * 128 + (bn4 << 2)] = bR[1];                  \
    }

    LDG_TILE(0);
    STS_TILE(0);
    __syncthreads();

    int KT = K >> 4;
    for (int kt = 0; kt < KT; kt++) {
        int cur = kt & 1;
        if (kt + 1 < KT) { LDG_TILE((kt + 1) << 4); }
        const float* Ab = As[cur];
        const float* Bb = Bs[cur];
#pragma unroll
        for (int kk = 0; kk < 16; kk++) {
            float4 a0 = *(const float4*)&Ab[kk * 128 + wm + lm];
            float4 a1 = *(const float4*)&Ab[kk * 128 + wm + lm + 16];
            ulonglong2 b0 = *(const ulonglong2*)&Bb[kk * 128 + wn + ln];
            ulonglong2 b1 = *(const ulonglong2*)&Bb[kk * 128 + wn + ln + 32];
            ull ap[8];
            ap[0] = dup2(a0.x); ap[1] = dup2(a0.y); ap[2] = dup2(a0.z); ap[3] = dup2(a0.w);
            ap[4] = dup2(a1.x); ap[5] = dup2(a1.y); ap[6] = dup2(a1.z); ap[7] = dup2(a1.w);
#pragma unroll
            for (int r = 0; r < 8; r++) {
                fma2(acc[r][0], ap[r], b0.x);
                fma2(acc[r][1], ap[r], b0.y);
                fma2(acc[r][2], ap[r], b1.x);
                fma2(acc[r][3], ap[r], b1.y);
            }
        }
        if (kt + 1 < KT) {
            STS_TILE(cur ^ 1);
            __syncthreads();
        }
    }

    float4 bias0 = *(const float4*)&bias[n0 + wn + ln];
    float4 bias1 = *(const float4*)&bias[n0 + wn + ln + 32];
#pragma unroll
    for (int r = 0; r < 8; r++) {
        int mrow = m0 + wm + lm + (r < 4 ? r : 12 + r);
        float2 p0 = unpk(acc[r][0]), p1 = unpk(acc[r][1]);
        float2 p2 = unpk(acc[r][2]), p3 = unpk(acc[r][3]);
        float4 v0 = {p0.x + bias0.x, p0.y + bias0.y, p1.x + bias0.z, p1.y + bias0.w};
        float4 v1 = {p2.x + bias1.x, p2.y + bias1.y, p3.x + bias1.z, p3.y + bias1.w};
        size_t crow = (size_t)mrow * G4 + n0 + wn + ln;
        *(float4*)&C[crow] = v0;
        *(float4*)&C[crow + 32] = v1;
    }
#undef LDG_TILE
#undef STS_TILE
}

// ---------------- persistent bidirectional LSTM scan (one layer) ----------------
// smem: h_s 128KB + u_s 64KB + mask_s 16KB = 208KB. zp0/zp1 alias h_s.
#define SMEM_STEP ((64 * 512 + 32 * 512 + 4096) * 4)

__global__ void __launch_bounds__(128) lstm_scan_kernel(
    const float* __restrict__ Uf, const float* __restrict__ Ub,
    float* dout, int out_is_y1)
{
    extern __shared__ float sm[];
    float* h_s = sm;                 // 64 rows * 512, chunk-swizzled by (b>>3)
    float* u_s = sm + 64 * 512;      // 32 rows * 512, chunk-swizzled by (j>>2)
    unsigned char* mask_s = (unsigned char*)(sm + 96 * 512);  // 16KB
    float* zp0 = sm;                 // aliases h_s (used after z-GEMM)
    float* zp1 = sm + 64 * 33;

    int tid = threadIdx.x;
    int dir = blockIdx.x >> 6;
    int cta = blockIdx.x & 63;
    int u0 = cta << 3;

    const float* U = dir ? Ub : Uf;
    const float* xz = dir ? g_xz_b : g_xz_f;
    float* outb = (out_is_y1 ? g_y1 : dout) + dir * D;
    unsigned* my_arr = &g_cta_arr[dir][cta][0];
    unsigned* my_cnt = &g_cnt[dir][0];

    // ---- stage U slice ONCE (32 cols x 512 k), swizzled ----
    for (int i = tid; i < 4096; i += 128) {
        int k = i >> 3, q = i & 7;
        int g = q >> 1, half = q & 1;
        int col = (g << 9) + u0 + (half << 2);
        float4 v = *(const float4*)&U[(size_t)k * G4 + col];
        int jb = (g << 3) + (half << 2);
        int chunk = k >> 2, klo = k & 3;
        const float* vp = (const float*)&v;
#pragma unroll
        for (int comp = 0; comp < 4; comp++) {
            int j = jb + comp;
            u_s[(j << 9) + (((chunk ^ ((j >> 2) & 7)) << 2) | klo)] = vp[comp];
        }
    }
    // ---- stage full mask ONCE (16KB) ----
    {
        const int4* msrc = (const int4*)g_mask;
        int4* mdst = (int4*)mask_s;
        for (int i = tid; i < M_ROWS / 16; i += 128) mdst[i] = msrc[i];
    }
    __syncthreads();   // one-time staging visible before step 0

    // persistent per-thread state: this thread owns (b = (tid+128j)>>3, u = tid&7)
    float c_reg[4]  = {0.f, 0.f, 0.f, 0.f};
    float h_reg[4]  = {0.f, 0.f, 0.f, 0.f};
    float po_reg[4] = {0.f, 0.f, 0.f, 0.f};

    int t = tid & 63, kg = tid >> 6;
    int tb = t >> 3, tc = t & 7;
    int b0 = tb << 3, c0 = tc << 2;
    int cbeg = kg << 6;
    const float* hbase = h_s + (b0 << 9);
    const float* ubase = u_s + (c0 << 9);
    int u = tid & 7;
    int cb = u0 + u;

    for (int s = 0; s < T; s++) {
        int ping = s & 1;
        int t_d = dir ? (T - 1 - s) : s;
        const float* h_in = g_h[ping] + dir * (B * D);
        float* h_out = g_h[ping ^ 1] + dir * (B * D);

        // ---- prefetch xz (L2, long latency — issued first) + mask from smem ----
        float xzr[4][4];
        unsigned mrv[4];
#pragma unroll
        for (int j = 0; j < 4; j++) {
            int b = (tid + (j << 7)) >> 3;
            int row = b * T + t_d;
            size_t xr = (size_t)row * G4;
            xzr[j][0] = __ldcg(&xz[xr + cb]);
            xzr[j][1] = __ldcg(&xz[xr + 512 + cb]);
            xzr[j][2] = __ldcg(&xz[xr + 1024 + cb]);
            xzr[j][3] = __ldcg(&xz[xr + 1536 + cb]);
            mrv[j] = mask_s[row];
        }

        // ---- stage h [64,512] (L2-fresh via .cg; L1 not coherent) ----
        for (int i = tid; i < 64 * 128; i += 128) {
            int b = i >> 7, c = i & 127;
            float4 v = __ldcg((const float4*)&h_in[(b << 9) + (c << 2)]);
            *(float4*)&h_s[(b << 9) + ((c ^ ((b >> 3) & 7)) << 2)] = v;
        }
        __syncthreads();

        // ---- z[64][32] = h @ U_slice (k split over 2 groups) ----
        ull acc[8][4];
#pragma unroll
        for (int r = 0; r < 8; r++)
#pragma unroll
            for (int ss = 0; ss < 4; ss++) acc[r][ss] = 0ULL;

#pragma unroll 2
        for (int ci = 0; ci < 64; ci++) {
            int c = cbeg + ci;
            int ph = (c ^ tb) << 2;
            int pu = (c ^ tc) << 2;
            ulonglong2 hv[8], uv[4];
#pragma unroll
            for (int r = 0; r < 8; r++) hv[r] = *(const ulonglong2*)&hbase[(r << 9) + ph];
#pragma unroll
            for (int ss = 0; ss < 4; ss++) uv[ss] = *(const ulonglong2*)&ubase[(ss << 9) + pu];
#pragma unroll
            for (int r = 0; r < 8; r++)
#pragma unroll
                for (int ss = 0; ss < 4; ss++) {
                    fma2(acc[r][ss], hv[r].x, uv[ss].x);
                    fma2(acc[r][ss], hv[r].y, uv[ss].y);
                }
        }
        __syncthreads();   // h_s reads done; zp aliasing now safe

        // ---- both k-groups write partials concurrently to disjoint buffers ----
        {
            float* zp = kg ? zp1 : zp0;
#pragma unroll
            for (int r = 0; r < 8; r++)
#pragma unroll
                for (int ss = 0; ss < 4; ss++) {
                    float2 f = unpk(acc[r][ss]);
                    zp[(b0 + r) * 33 + c0 + ss] = f.x + f.y;
                }
        }
        __syncthreads();

        // ---- gates + state update (register-resident c/h/prev) ----
#pragma unroll
        for (int j = 0; j < 4; j++) {
            int b = (tid + (j << 7)) >> 3;
            float zi = zp0[b * 33 + u]      + zp1[b * 33 + u]      + xzr[j][0];
            float zf = zp0[b * 33 + 8 + u]  + zp1[b * 33 + 8 + u]  + xzr[j][1];
            float zg = zp0[b * 33 + 16 + u] + zp1[b * 33 + 16 + u] + xzr[j][2];
            float zo = zp0[b * 33 + 24 + u] + zp1[b * 33 + 24 + u] + xzr[j][3];
            float iv = 1.0f / (1.0f + expf(-zi));
            float fv = 1.0f / (1.0f + expf(-zf));
            float gv = tanhf(zg);
            float ov = 1.0f / (1.0f + expf(-zo));
            float c_new = fv * c_reg[j] + iv * gv;
            float h_new = ov * tanhf(c_new);
            bool m = mrv[j] != 0u;
            c_reg[j]  = m ? c_new : c_reg[j];
            h_reg[j]  = m ? h_new : h_reg[j];
            po_reg[j] = m ? h_new : po_reg[j];
            h_out[b * D + cb] = h_reg[j];
        }

        bool not_last = (s + 1 < T);
        if (not_last) {
            // EVERY thread arrives with a release-reduction: its own h_out
            // stores are hardware-guaranteed visible before its increment is.
            red_release_add(my_arr, 1u);
        }

        // ---- per-timestep output write (overlaps barrier) ----
#pragma unroll
        for (int j = 0; j < 4; j++) {
            int b = (tid + (j << 7)) >> 3;
            int row = b * T + t_d;
            outb[(size_t)row * 1024 + cb] = po_reg[j];
        }

        if (not_last) {
            if (tid == 0) {
                unsigned tgt_cta = 128u * (unsigned)(s + 1);
                while (ld_acquire(my_arr) < tgt_cta) {}
                red_release_add(my_cnt, 1u);
                unsigned tgt_all = 64u * (unsigned)(s + 1);
                while (ld_acquire(my_cnt) < tgt_all) {}
            }
            __syncthreads();
        }
    }

    // final cell state
#pragma unroll
    for (int j = 0; j < 4; j++) {
        int b = (tid + (j << 7)) >> 3;
        g_c[dir * (B * D) + b * D + cb] = c_reg[j];
    }
}

// ---------------- final hidden/cell concat ----------------
__global__ void finalize_kernel(float* dout, int out_size) {
    int i = blockIdx.x * blockDim.x + threadIdx.x;
    if (i >= B * 2 * D) return;
    size_t hoff = (size_t)B * T * 1024;
    if ((size_t)out_size < hoff + 2 * (size_t)(B * 2 * D)) return;
    int b = i >> 10, j = i & 1023;
    int dir = j >> 9, u = j & 511;
    int sidx = dir * (B * D) + b * D + u;
    dout[hoff + i] = g_h[0][sidx];   // 256 steps => final ping = 0
    dout[hoff + B * 2 * D + i] = g_c[sidx];
}

// ---------------- host orchestration ----------------
extern "C" void kernel_launch(void* const* d_in, const int* in_sizes, int n_in,
                              void* d_out, int out_size) {
    const float* X   = (const float*)d_in[0];
    const float* Wf1 = (const float*)d_in[1];
    const float* Uf1 = (const float*)d_in[2];
    const float* bf1 = (const float*)d_in[3];
    const float* Wb1 = (const float*)d_in[4];
    const float* Ub1 = (const float*)d_in[5];
    const float* bb1 = (const float*)d_in[6];
    const float* Wf2 = (const float*)d_in[7];
    const float* Uf2 = (const float*)d_in[8];
    const float* bf2 = (const float*)d_in[9];
    const float* Wb2 = (const float*)d_in[10];
    const float* Ub2 = (const float*)d_in[11];
    const float* bb2 = (const float*)d_in[12];
    float* out = (float*)d_out;

    cudaFuncSetAttribute(lstm_scan_kernel,
                         cudaFuncAttributeMaxDynamicSharedMemorySize, SMEM_STEP);

    dim3 ggrid(G4 / 128, M_ROWS / 128);

    // launch order puts scans at positions 4 and 8 (ncu capture slots)
    maskinit_kernel<<<M_ROWS / 4, 128>>>(X);                       // 1
    gemm_bias_kernel<<<ggrid, 256>>>(X, 0, Wf1, bf1, 0, 512);      // 2
    gemm_bias_kernel<<<ggrid, 256>>>(X, 0, Wb1, bb1, 1, 512);      // 3
    lstm_scan_kernel<<<128, 128, SMEM_STEP>>>(Uf1, Ub1, out, 1);   // 4

    gemm_bias_kernel<<<ggrid, 256>>>(nullptr, 1, Wf2, bf2, 0, 1024); // 5
    gemm_bias_kernel<<<ggrid, 256>>>(nullptr, 1, Wb2, bb2, 1, 1024); // 6
    maskinit_kernel<<<M_ROWS / 4, 128>>>(X);                         // 7
    lstm_scan_kernel<<<128, 128, SMEM_STEP>>>(Uf2, Ub2, out, 0);     // 8

    finalize_kernel<<<256, 256>>>(out, out_size);                    // 9
}

// round 8
// speedup vs baseline: 1.2530x; 1.2530x over previous
#include <cuda_runtime.h>
#include <math.h>

#define B 64
#define T 256
#define D 512
#define G4 2048
#define M_ROWS (B * T)   // 16384
#define DIN2 1024

typedef unsigned long long ull;

// ---------------- f32x2 helpers ----------------
__device__ __forceinline__ void fma2(ull &d, ull a, ull b) {
    asm("fma.rn.f32x2 %0, %1, %2, %0;" : "+l"(d) : "l"(a), "l"(b));
}
__device__ __forceinline__ ull dup2(float v) {
    ull r; unsigned u = __float_as_uint(v);
    asm("mov.b64 %0, {%1, %1};" : "=l"(r) : "r"(u));
    return r;
}
__device__ __forceinline__ float2 unpk(ull v) {
    float2 f;
    asm("mov.b64 {%0, %1}, %2;" : "=f"(f.x), "=f"(f.y) : "l"(v));
    return f;
}

// ---------------- release/acquire barrier primitives ----------------
__device__ __forceinline__ void red_release_add(unsigned* p, unsigned v) {
    asm volatile("red.release.gpu.global.add.u32 [%0], %1;"
                 :: "l"(p), "r"(v) : "memory");
}
__device__ __forceinline__ unsigned ld_acquire(const unsigned* p) {
    unsigned v;
    asm volatile("ld.acquire.gpu.global.u32 %0, [%1];"
                 : "=r"(v) : "l"(p) : "memory");
    return v;
}

// ---------------- device scratch ----------------
__device__ float g_xz_f[(size_t)M_ROWS * G4];
__device__ float g_xz_b[(size_t)M_ROWS * G4];
__device__ float g_y1[(size_t)M_ROWS * DIN2];
__device__ float g_h[2][2 * B * D];
__device__ float g_c[2 * B * D];
__device__ unsigned char g_mask[M_ROWS];
// monotonic arrival counters, padded to 128B per counter
__device__ unsigned g_cta_arr[2][64][32];   // [dir][cta][pad]
__device__ unsigned g_cnt[2][32];           // [dir][pad]

// ---------------- fused: mask + zero h + barrier reset ----------------
__global__ void maskinit_kernel(const float* __restrict__ X) {
    int tid = threadIdx.x;
    int gidx = blockIdx.x * 128 + tid;
    if (gidx < 2 * 2 * B * D) ((float*)g_h)[gidx] = 0.0f;
    if (gidx < 2 * 64 * 32) ((unsigned*)g_cta_arr)[gidx] = 0u;
    if (gidx < 2 * 32) ((unsigned*)g_cnt)[gidx] = 0u;
    int row = blockIdx.x * 4 + (tid >> 5);
    int lane = tid & 31;
    const float* p = X + (size_t)row * D;
    int any = 0;
    for (int k = lane; k < D; k += 32) any |= (p[k] != 0.0f);
    any = __any_sync(0xffffffffu, any);
    if (lane == 0) g_mask[row] = (unsigned char)any;
}

// ---------------- GEMM: C[M,2048] = A[M,K] @ W[K,2048] + bias ----------------
__global__ void __launch_bounds__(256, 2) gemm_bias_kernel(
    const float* __restrict__ Aext, int a_is_y1,
    const float* __restrict__ W, const float* __restrict__ bias,
    int c_sel, int K)
{
    const float* A = a_is_y1 ? g_y1 : Aext;
    float* C = c_sel ? g_xz_b : g_xz_f;

    __shared__ float As[2][16 * 128];
    __shared__ float Bs[2][16 * 128];

    int tid = threadIdx.x;
    int m0 = blockIdx.y << 7, n0 = blockIdx.x << 7;
    int warp = tid >> 5, lane = tid & 31;
    int wm = (warp & 3) << 5, wn = (warp >> 2) << 6;
    int lm = (lane >> 3) << 2, ln = (lane & 7) << 2;
    int am = tid & 127, akg = tid >> 7;
    int bn4 = tid & 31, bk0 = tid >> 5;

    ull acc[8][4];
#pragma unroll
    for (int r = 0; r < 8; r++)
#pragma unroll
        for (int s = 0; s < 4; s++) acc[r][s] = 0ULL;

    float4 aR[2], bR[2];
    const size_t arow = (size_t)(m0 + am) * K;

#define LDG_TILE(k0)                                                          \
    aR[0] = *(const float4*)&A[arow + (k0) + (akg << 2)];                     \
    aR[1] = *(const float4*)&A[arow + (k0) + ((akg + 2) << 2)];               \
    bR[0] = *(const float4*)&W[(size_t)((k0) + bk0) * G4 + n0 + (bn4 << 2)];  \
    bR[1] = *(const float4*)&W[(size_t)((k0) + bk0 + 8) * G4 + n0 + (bn4 << 2)];

#define STS_TILE(buf)                                                         \
    {                                                                         \
        float* Ad = As[buf]; float* Bd = Bs[buf];                             \
        Ad[((akg << 2) + 0) * 128 + am] = aR[0].x;                            \
        Ad[((akg << 2) + 1) * 128 + am] = aR[0].y;                            \
        Ad[((akg << 2) + 2) * 128 + am] = aR[0].z;                            \
        Ad[((akg << 2) + 3) * 128 + am] = aR[0].w;                            \
        Ad[(((akg + 2) << 2) + 0) * 128 + am] = aR[1].x;                      \
        Ad[(((akg + 2) << 2) + 1) * 128 + am] = aR[1].y;                      \
        Ad[(((akg + 2) << 2) + 2) * 128 + am] = aR[1].z;                      \
        Ad[(((akg + 2) << 2) + 3) * 128 + am] = aR[1].w;                      \
        *(float4*)&Bd[bk0 * 128 + (bn4 << 2)] = bR[0];                        \
        *(float4*)&Bd[(bk0 + 8) * 128 + (bn4 << 2)] = bR[1];                  \
    }

    LDG_TILE(0);
    STS_TILE(0);
    __syncthreads();

    int KT = K >> 4;
    for (int kt = 0; kt < KT; kt++) {
        int cur = kt & 1;
        if (kt + 1 < KT) { LDG_TILE((kt + 1) << 4); }
        const float* Ab = As[cur];
        const float* Bb = Bs[cur];
#pragma unroll
        for (int kk = 0; kk < 16; kk++) {
            float4 a0 = *(const float4*)&Ab[kk * 128 + wm + lm];
            float4 a1 = *(const float4*)&Ab[kk * 128 + wm + lm + 16];
            ulonglong2 b0 = *(const ulonglong2*)&Bb[kk * 128 + wn + ln];
            ulonglong2 b1 = *(const ulonglong2*)&Bb[kk * 128 + wn + ln + 32];
            ull ap[8];
            ap[0] = dup2(a0.x); ap[1] = dup2(a0.y); ap[2] = dup2(a0.z); ap[3] = dup2(a0.w);
            ap[4] = dup2(a1.x); ap[5] = dup2(a1.y); ap[6] = dup2(a1.z); ap[7] = dup2(a1.w);
#pragma unroll
            for (int r = 0; r < 8; r++) {
                fma2(acc[r][0], ap[r], b0.x);
                fma2(acc[r][1], ap[r], b0.y);
                fma2(acc[r][2], ap[r], b1.x);
                fma2(acc[r][3], ap[r], b1.y);
            }
        }
        if (kt + 1 < KT) {
            STS_TILE(cur ^ 1);
            __syncthreads();
        }
    }

    float4 bias0 = *(const float4*)&bias[n0 + wn + ln];
    float4 bias1 = *(const float4*)&bias[n0 + wn + ln + 32];
#pragma unroll
    for (int r = 0; r < 8; r++) {
        int mrow = m0 + wm + lm + (r < 4 ? r : 12 + r);
        float2 p0 = unpk(acc[r][0]), p1 = unpk(acc[r][1]);
        float2 p2 = unpk(acc[r][2]), p3 = unpk(acc[r][3]);
        float4 v0 = {p0.x + bias0.x, p0.y + bias0.y, p1.x + bias0.z, p1.y + bias0.w};
        float4 v1 = {p2.x + bias1.x, p2.y + bias1.y, p3.x + bias1.z, p3.y + bias1.w};
        size_t crow = (size_t)mrow * G4 + n0 + wn + ln;
        *(float4*)&C[crow] = v0;
        *(float4*)&C[crow + 32] = v1;
    }
#undef LDG_TILE
#undef STS_TILE
}

// ---------------- persistent bidirectional LSTM scan (one layer) ----------------
// 128 CTAs (dir = blk>>6; 8 hidden units = 32 gate cols each), 256 THREADS.
// z-GEMM: k split over 4 slabs of 128; thread tile 8(b) x 4(col).
// smem: h_s 128KB + u_s 64KB + mask_s 16KB = 208KB. zp[4] alias h_s (34KB).
#define SMEM_STEP ((64 * 512 + 32 * 512 + 4096) * 4)

__global__ void __launch_bounds__(256) lstm_scan_kernel(
    const float* __restrict__ Uf, const float* __restrict__ Ub,
    float* dout, int out_is_y1)
{
    extern __shared__ float sm[];
    float* h_s = sm;                 // 64 rows * 512, chunk-swizzled by (b>>3)
    float* u_s = sm + 64 * 512;      // 32 rows * 512, chunk-swizzled by (j>>2)
    unsigned char* mask_s = (unsigned char*)(sm + 96 * 512);  // 16KB
    float* zp = sm;                  // 4 partial buffers [64][33], alias h_s

    int tid = threadIdx.x;
    int dir = blockIdx.x >> 6;
    int cta = blockIdx.x & 63;
    int u0 = cta << 3;

    const float* U = dir ? Ub : Uf;
    const float* xz = dir ? g_xz_b : g_xz_f;
    float* outb = (out_is_y1 ? g_y1 : dout) + dir * D;
    unsigned* my_arr = &g_cta_arr[dir][cta][0];
    unsigned* my_cnt = &g_cnt[dir][0];

    // ---- stage U slice ONCE (32 cols x 512 k), swizzled ----
    for (int i = tid; i < 4096; i += 256) {
        int k = i >> 3, q = i & 7;
        int g = q >> 1, half = q & 1;
        int col = (g << 9) + u0 + (half << 2);
        float4 v = *(const float4*)&U[(size_t)k * G4 + col];
        int jb = (g << 3) + (half << 2);
        int chunk = k >> 2, klo = k & 3;
        const float* vp = (const float*)&v;
#pragma unroll
        for (int comp = 0; comp < 4; comp++) {
            int j = jb + comp;
            u_s[(j << 9) + (((chunk ^ ((j >> 2) & 7)) << 2) | klo)] = vp[comp];
        }
    }
    // ---- stage full mask ONCE (16KB) ----
    {
        const int4* msrc = (const int4*)g_mask;
        int4* mdst = (int4*)mask_s;
        for (int i = tid; i < M_ROWS / 16; i += 256) mdst[i] = msrc[i];
    }
    __syncthreads();

    // persistent per-thread state: thread owns elems e = tid, tid+256
    // (e>>3 = batch, e&7 = unit)
    float c_reg[2]  = {0.f, 0.f};
    float h_reg[2]  = {0.f, 0.f};
    float po_reg[2] = {0.f, 0.f};

    int slab = tid >> 6;           // 4 k-slabs of 128 k
    int t = tid & 63;
    int tb = t >> 3, tc = t & 7;   // 8 row-groups x 8 col-groups
    int b0 = tb << 3, c0 = tc << 2;
    int cbeg = slab << 5;          // chunk index base (chunk = k>>2)
    const float* hbase = h_s + (b0 << 9);
    const float* ubase = u_s + (c0 << 9);
    float* myzp = zp + slab * (64 * 33);
    int u = tid & 7;
    int cb = u0 + u;

    for (int s = 0; s < T; s++) {
        int ping = s & 1;
        int t_d = dir ? (T - 1 - s) : s;
        const float* h_in = g_h[ping] + dir * (B * D);
        float* h_out = g_h[ping ^ 1] + dir * (B * D);

        // ---- prefetch xz (long latency — issued first) + mask from smem ----
        float xzr[2][4];
        unsigned mrv[2];
#pragma unroll
        for (int j = 0; j < 2; j++) {
            int b = (tid + (j << 8)) >> 3;
            int row = b * T + t_d;
            size_t xr = (size_t)row * G4;
            xzr[j][0] = __ldcg(&xz[xr + cb]);
            xzr[j][1] = __ldcg(&xz[xr + 512 + cb]);
            xzr[j][2] = __ldcg(&xz[xr + 1024 + cb]);
            xzr[j][3] = __ldcg(&xz[xr + 1536 + cb]);
            mrv[j] = mask_s[row];
        }

        // ---- stage h [64,512] (L2-fresh via .cg; L1 not coherent) ----
        for (int i = tid; i < 64 * 128; i += 256) {
            int b = i >> 7, c = i & 127;
            float4 v = __ldcg((const float4*)&h_in[(b << 9) + (c << 2)]);
            *(float4*)&h_s[(b << 9) + ((c ^ ((b >> 3) & 7)) << 2)] = v;
        }
        __syncthreads();

        // ---- z[64][32] partial = h @ U_slice over this slab's 128 k ----
        ull acc[8][4];
#pragma unroll
        for (int r = 0; r < 8; r++)
#pragma unroll
            for (int ss = 0; ss < 4; ss++) acc[r][ss] = 0ULL;

#pragma unroll 4
        for (int ci = 0; ci < 32; ci++) {
            int c = cbeg + ci;
            int ph = (c ^ tb) << 2;
            int pu = (c ^ tc) << 2;
            ulonglong2 hv[8], uv[4];
#pragma unroll
            for (int r = 0; r < 8; r++) hv[r] = *(const ulonglong2*)&hbase[(r << 9) + ph];
#pragma unroll
            for (int ss = 0; ss < 4; ss++) uv[ss] = *(const ulonglong2*)&ubase[(ss << 9) + pu];
#pragma unroll
            for (int r = 0; r < 8; r++)
#pragma unroll
                for (int ss = 0; ss < 4; ss++) {
                    fma2(acc[r][ss], hv[r].x, uv[ss].x);
                    fma2(acc[r][ss], hv[r].y, uv[ss].y);
                }
        }
        __syncthreads();   // h_s reads done; zp aliasing now safe

        // ---- all 4 slabs write partials concurrently (disjoint buffers) ----
#pragma unroll
        for (int r = 0; r < 8; r++)
#pragma unroll
            for (int ss = 0; ss < 4; ss++) {
                float2 f = unpk(acc[r][ss]);
                myzp[(b0 + r) * 33 + c0 + ss] = f.x + f.y;
            }
        __syncthreads();

        // ---- gates + state update (register-resident c/h/prev) ----
#pragma unroll
        for (int j = 0; j < 2; j++) {
            int b = (tid + (j << 8)) >> 3;
            int zrow = b * 33 + u;
            float zi = xzr[j][0], zf = xzr[j][1], zg = xzr[j][2], zo = xzr[j][3];
#pragma unroll
            for (int p = 0; p < 4; p++) {
                const float* zb = zp + p * (64 * 33);
                zi += zb[zrow];
                zf += zb[zrow + 8];
                zg += zb[zrow + 16];
                zo += zb[zrow + 24];
            }
            float iv = 1.0f / (1.0f + expf(-zi));
            float fv = 1.0f / (1.0f + expf(-zf));
            float gv = tanhf(zg);
            float ov = 1.0f / (1.0f + expf(-zo));
            float c_new = fv * c_reg[j] + iv * gv;
            float h_new = ov * tanhf(c_new);
            bool m = mrv[j] != 0u;
            c_reg[j]  = m ? c_new : c_reg[j];
            h_reg[j]  = m ? h_new : h_reg[j];
            po_reg[j] = m ? h_new : po_reg[j];
            h_out[b * D + cb] = h_reg[j];
        }

        bool not_last = (s + 1 < T);
        if (not_last) {
            // every thread: release-arrive (orders own h_out stores first)
            red_release_add(my_arr, 1u);
        }

        // ---- per-timestep output write (overlaps barrier) ----
#pragma unroll
        for (int j = 0; j < 2; j++) {
            int b = (tid + (j << 8)) >> 3;
            int row = b * T + t_d;
            outb[(size_t)row * 1024 + cb] = po_reg[j];
        }

        if (not_last) {
            if (tid == 0) {
                unsigned tgt_cta = 256u * (unsigned)(s + 1);
                while (ld_acquire(my_arr) < tgt_cta) __nanosleep(64);
                red_release_add(my_cnt, 1u);
                unsigned tgt_all = 64u * (unsigned)(s + 1);
                while (ld_acquire(my_cnt) < tgt_all) __nanosleep(64);
            }
            __syncthreads();
        }
    }

    // final cell state
#pragma unroll
    for (int j = 0; j < 2; j++) {
        int b = (tid + (j << 8)) >> 3;
        g_c[dir * (B * D) + b * D + cb] = c_reg[j];
    }
}

// ---------------- final hidden/cell concat ----------------
__global__ void finalize_kernel(float* dout, int out_size) {
    int i = blockIdx.x * blockDim.x + threadIdx.x;
    if (i >= B * 2 * D) return;
    size_t hoff = (size_t)B * T * 1024;
    if ((size_t)out_size < hoff + 2 * (size_t)(B * 2 * D)) return;
    int b = i >> 10, j = i & 1023;
    int dir = j >> 9, u = j & 511;
    int sidx = dir * (B * D) + b * D + u;
    dout[hoff + i] = g_h[0][sidx];   // 256 steps => final ping = 0
    dout[hoff + B * 2 * D + i] = g_c[sidx];
}

// ---------------- host orchestration ----------------
extern "C" void kernel_launch(void* const* d_in, const int* in_sizes, int n_in,
                              void* d_out, int out_size) {
    const float* X   = (const float*)d_in[0];
    const float* Wf1 = (const float*)d_in[1];
    const float* Uf1 = (const float*)d_in[2];
    const float* bf1 = (const float*)d_in[3];
    const float* Wb1 = (const float*)d_in[4];
    const float* Ub1 = (const float*)d_in[5];
    const float* bb1 = (const float*)d_in[6];
    const float* Wf2 = (const float*)d_in[7];
    const float* Uf2 = (const float*)d_in[8];
    const float* bf2 = (const float*)d_in[9];
    const float* Wb2 = (const float*)d_in[10];
    const float* Ub2 = (const float*)d_in[11];
    const float* bb2 = (const float*)d_in[12];
    float* out = (float*)d_out;

    cudaFuncSetAttribute(lstm_scan_kernel,
                         cudaFuncAttributeMaxDynamicSharedMemorySize, SMEM_STEP);

    dim3 ggrid(G4 / 128, M_ROWS / 128);

    // launch order puts scans at positions 4 and 8 (ncu capture slots)
    maskinit_kernel<<<M_ROWS / 4, 128>>>(X);                       // 1
    gemm_bias_kernel<<<ggrid, 256>>>(X, 0, Wf1, bf1, 0, 512);      // 2
    gemm_bias_kernel<<<ggrid, 256>>>(X, 0, Wb1, bb1, 1, 512);      // 3
    lstm_scan_kernel<<<128, 256, SMEM_STEP>>>(Uf1, Ub1, out, 1);   // 4

    gemm_bias_kernel<<<ggrid, 256>>>(nullptr, 1, Wf2, bf2, 0, 1024); // 5
    gemm_bias_kernel<<<ggrid, 256>>>(nullptr, 1, Wb2, bb2, 1, 1024); // 6
    maskinit_kernel<<<M_ROWS / 4, 128>>>(X);                         // 7
    lstm_scan_kernel<<<128, 256, SMEM_STEP>>>(Uf2, Ub2, out, 0);     // 8

    finalize_kernel<<<256, 256>>>(out, out_size);                    // 9
}

// round 9
// speedup vs baseline: 1.2580x; 1.0040x over previous
#include <cuda_runtime.h>
#include <math.h>

#define B 64
#define T 256
#define D 512
#define G4 2048
#define M_ROWS (B * T)   // 16384
#define DIN2 1024

typedef unsigned long long ull;

// ---------------- f32x2 helpers ----------------
__device__ __forceinline__ void fma2(ull &d, ull a, ull b) {
    asm("fma.rn.f32x2 %0, %1, %2, %0;" : "+l"(d) : "l"(a), "l"(b));
}
__device__ __forceinline__ ull dup2(float v) {
    ull r; unsigned u = __float_as_uint(v);
    asm("mov.b64 %0, {%1, %1};" : "=l"(r) : "r"(u));
    return r;
}
__device__ __forceinline__ float2 unpk(ull v) {
    float2 f;
    asm("mov.b64 {%0, %1}, %2;" : "=f"(f.x), "=f"(f.y) : "l"(v));
    return f;
}

// ---------------- release/acquire barrier primitives ----------------
__device__ __forceinline__ void red_release_add(unsigned* p, unsigned v) {
    asm volatile("red.release.gpu.global.add.u32 [%0], %1;"
                 :: "l"(p), "r"(v) : "memory");
}
__device__ __forceinline__ unsigned ld_acquire(const unsigned* p) {
    unsigned v;
    asm volatile("ld.acquire.gpu.global.u32 %0, [%1];"
                 : "=r"(v) : "l"(p) : "memory");
    return v;
}

// ---------------- device scratch ----------------
__device__ float g_xz_f[(size_t)M_ROWS * G4];
__device__ float g_xz_b[(size_t)M_ROWS * G4];
__device__ float g_y1[(size_t)M_ROWS * DIN2];
__device__ float g_h[2][2 * B * D];
__device__ float g_c[2 * B * D];
__device__ unsigned char g_mask[M_ROWS];
// monotonic arrival counters, padded to 128B per counter
__device__ unsigned g_cta_arr[2][64][32];   // [dir][cta][pad]
__device__ unsigned g_cnt[2][32];           // [dir][pad]

// ---------------- fused: mask + zero h + barrier reset ----------------
__global__ void maskinit_kernel(const float* __restrict__ X) {
    int tid = threadIdx.x;
    int gidx = blockIdx.x * 128 + tid;
    if (gidx < 2 * 2 * B * D) ((float*)g_h)[gidx] = 0.0f;
    if (gidx < 2 * 64 * 32) ((unsigned*)g_cta_arr)[gidx] = 0u;
    if (gidx < 2 * 32) ((unsigned*)g_cnt)[gidx] = 0u;
    int row = blockIdx.x * 4 + (tid >> 5);
    int lane = tid & 31;
    const float* p = X + (size_t)row * D;
    int any = 0;
    for (int k = lane; k < D; k += 32) any |= (p[k] != 0.0f);
    any = __any_sync(0xffffffffu, any);
    if (lane == 0) g_mask[row] = (unsigned char)any;
}

// ---------------- GEMM: C[M,2048] = A[M,K] @ W[K,2048] + bias ----------------
__global__ void __launch_bounds__(256, 2) gemm_bias_kernel(
    const float* __restrict__ Aext, int a_is_y1,
    const float* __restrict__ W, const float* __restrict__ bias,
    int c_sel, int K)
{
    const float* A = a_is_y1 ? g_y1 : Aext;
    float* C = c_sel ? g_xz_b : g_xz_f;

    __shared__ float As[2][16 * 128];
    __shared__ float Bs[2][16 * 128];

    int tid = threadIdx.x;
    int m0 = blockIdx.y << 7, n0 = blockIdx.x << 7;
    int warp = tid >> 5, lane = tid & 31;
    int wm = (warp & 3) << 5, wn = (warp >> 2) << 6;
    int lm = (lane >> 3) << 2, ln = (lane & 7) << 2;
    int am = tid & 127, akg = tid >> 7;
    int bn4 = tid & 31, bk0 = tid >> 5;

    ull acc[8][4];
#pragma unroll
    for (int r = 0; r < 8; r++)
#pragma unroll
        for (int s = 0; s < 4; s++) acc[r][s] = 0ULL;

    float4 aR[2], bR[2];
    const size_t arow = (size_t)(m0 + am) * K;

#define LDG_TILE(k0)                                                          \
    aR[0] = *(const float4*)&A[arow + (k0) + (akg << 2)];                     \
    aR[1] = *(const float4*)&A[arow + (k0) + ((akg + 2) << 2)];               \
    bR[0] = *(const float4*)&W[(size_t)((k0) + bk0) * G4 + n0 + (bn4 << 2)];  \
    bR[1] = *(const float4*)&W[(size_t)((k0) + bk0 + 8) * G4 + n0 + (bn4 << 2)];

#define STS_TILE(buf)                                                         \
    {                                                                         \
        float* Ad = As[buf]; float* Bd = Bs[buf];                             \
        Ad[((akg << 2) + 0) * 128 + am] = aR[0].x;                            \
        Ad[((akg << 2) + 1) * 128 + am] = aR[0].y;                            \
        Ad[((akg << 2) + 2) * 128 + am] = aR[0].z;                            \
        Ad[((akg << 2) + 3) * 128 + am] = aR[0].w;                            \
        Ad[(((akg + 2) << 2) + 0) * 128 + am] = aR[1].x;                      \
        Ad[(((akg + 2) << 2) + 1) * 128 + am] = aR[1].y;                      \
        Ad[(((akg + 2) << 2) + 2) * 128 + am] = aR[1].z;                      \
        Ad[(((akg + 2) << 2) + 3) * 128 + am] = aR[1].w;                      \
        *(float4*)&Bd[bk0 * 128 + (bn4 << 2)] = bR[0];                        \
        *(float4*)&Bd[(bk0 + 8) * 128 + (bn4 << 2)] = bR[1];                  \
    }

    LDG_TILE(0);
    STS_TILE(0);
    __syncthreads();

    int KT = K >> 4;
    for (int kt = 0; kt < KT; kt++) {
        int cur = kt & 1;
        if (kt + 1 < KT) { LDG_TILE((kt + 1) << 4); }
        const float* Ab = As[cur];
        const float* Bb = Bs[cur];
#pragma unroll
        for (int kk = 0; kk < 16; kk++) {
            float4 a0 = *(const float4*)&Ab[kk * 128 + wm + lm];
            float4 a1 = *(const float4*)&Ab[kk * 128 + wm + lm + 16];
            ulonglong2 b0 = *(const ulonglong2*)&Bb[kk * 128 + wn + ln];
            ulonglong2 b1 = *(const ulonglong2*)&Bb[kk * 128 + wn + ln + 32];
            ull ap[8];
            ap[0] = dup2(a0.x); ap[1] = dup2(a0.y); ap[2] = dup2(a0.z); ap[3] = dup2(a0.w);
            ap[4] = dup2(a1.x); ap[5] = dup2(a1.y); ap[6] = dup2(a1.z); ap[7] = dup2(a1.w);
#pragma unroll
            for (int r = 0; r < 8; r++) {
                fma2(acc[r][0], ap[r], b0.x);
                fma2(acc[r][1], ap[r], b0.y);
                fma2(acc[r][2], ap[r], b1.x);
                fma2(acc[r][3], ap[r], b1.y);
            }
        }
        if (kt + 1 < KT) {
            STS_TILE(cur ^ 1);
            __syncthreads();
        }
    }

    float4 bias0 = *(const float4*)&bias[n0 + wn + ln];
    float4 bias1 = *(const float4*)&bias[n0 + wn + ln + 32];
#pragma unroll
    for (int r = 0; r < 8; r++) {
        int mrow = m0 + wm + lm + (r < 4 ? r : 12 + r);
        float2 p0 = unpk(acc[r][0]), p1 = unpk(acc[r][1]);
        float2 p2 = unpk(acc[r][2]), p3 = unpk(acc[r][3]);
        float4 v0 = {p0.x + bias0.x, p0.y + bias0.y, p1.x + bias0.z, p1.y + bias0.w};
        float4 v1 = {p2.x + bias1.x, p2.y + bias1.y, p3.x + bias1.z, p3.y + bias1.w};
        size_t crow = (size_t)mrow * G4 + n0 + wn + ln;
        *(float4*)&C[crow] = v0;
        *(float4*)&C[crow + 32] = v1;
    }
#undef LDG_TILE
#undef STS_TILE
}

// ---------------- persistent bidirectional LSTM scan (one layer) ----------------
// 128 CTAs (dir = blk>>6; 8 hidden units = 32 gate cols each), 512 THREADS.
// z-GEMM: k split over 8 slabs of 64; thread tile 8(b) x 4(col).
// smem: h_s 128KB + u_s 64KB + mask_s 16KB = 208KB. zp[8] (67.6KB) alias h_s.
#define SMEM_STEP ((64 * 512 + 32 * 512 + 4096) * 4)

__global__ void __launch_bounds__(512) lstm_scan_kernel(
    const float* __restrict__ Uf, const float* __restrict__ Ub,
    float* dout, int out_is_y1)
{
    extern __shared__ float sm[];
    float* h_s = sm;                 // 64 rows * 512, chunk-swizzled by (b>>3)
    float* u_s = sm + 64 * 512;      // 32 rows * 512, chunk-swizzled by (j>>2)
    unsigned char* mask_s = (unsigned char*)(sm + 96 * 512);  // 16KB
    float* zp = sm;                  // 8 partial buffers [64][33], alias h_s

    int tid = threadIdx.x;
    int dir = blockIdx.x >> 6;
    int cta = blockIdx.x & 63;
    int u0 = cta << 3;

    const float* U = dir ? Ub : Uf;
    const float* xz = dir ? g_xz_b : g_xz_f;
    float* outb = (out_is_y1 ? g_y1 : dout) + dir * D;
    unsigned* my_arr = &g_cta_arr[dir][cta][0];
    unsigned* my_cnt = &g_cnt[dir][0];

    // ---- stage U slice ONCE (32 cols x 512 k), swizzled ----
    for (int i = tid; i < 4096; i += 512) {
        int k = i >> 3, q = i & 7;
        int g = q >> 1, half = q & 1;
        int col = (g << 9) + u0 + (half << 2);
        float4 v = *(const float4*)&U[(size_t)k * G4 + col];
        int jb = (g << 3) + (half << 2);
        int chunk = k >> 2, klo = k & 3;
        const float* vp = (const float*)&v;
#pragma unroll
        for (int comp = 0; comp < 4; comp++) {
            int j = jb + comp;
            u_s[(j << 9) + (((chunk ^ ((j >> 2) & 7)) << 2) | klo)] = vp[comp];
        }
    }
    // ---- stage full mask ONCE (16KB) ----
    {
        const int4* msrc = (const int4*)g_mask;
        int4* mdst = (int4*)mask_s;
        for (int i = tid; i < M_ROWS / 16; i += 512) mdst[i] = msrc[i];
    }
    __syncthreads();

    // persistent per-thread state: thread owns elem e = tid (b = tid>>3, u = tid&7)
    float c_reg = 0.f, h_reg = 0.f, po_reg = 0.f;

    int slab = tid >> 6;           // 8 k-slabs of 64 k
    int t = tid & 63;
    int tb = t >> 3, tc = t & 7;   // 8 row-groups x 8 col-groups
    int b0 = tb << 3, c0 = tc << 2;
    int cbeg = slab << 4;          // chunk index base (chunk = k>>2); 16 chunks/slab
    const float* hbase = h_s + (b0 << 9);
    const float* ubase = u_s + (c0 << 9);
    float* myzp = zp + slab * (64 * 33);
    int u = tid & 7;
    int gb = tid >> 3;             // gate-phase batch index (0..63)
    int cb = u0 + u;

    for (int s = 0; s < T; s++) {
        int ping = s & 1;
        int t_d = dir ? (T - 1 - s) : s;
        const float* h_in = g_h[ping] + dir * (B * D);
        float* h_out = g_h[ping ^ 1] + dir * (B * D);

        // ---- prefetch xz (long latency — issued first) + mask from smem ----
        float xzr0, xzr1, xzr2, xzr3;
        unsigned mrv;
        {
            int row = gb * T + t_d;
            size_t xr = (size_t)row * G4;
            xzr0 = __ldcg(&xz[xr + cb]);
            xzr1 = __ldcg(&xz[xr + 512 + cb]);
            xzr2 = __ldcg(&xz[xr + 1024 + cb]);
            xzr3 = __ldcg(&xz[xr + 1536 + cb]);
            mrv = mask_s[row];
        }

        // ---- stage h [64,512] (L2-fresh via .cg; L1 not coherent) ----
        for (int i = tid; i < 64 * 128; i += 512) {
            int b = i >> 7, c = i & 127;
            float4 v = __ldcg((const float4*)&h_in[(b << 9) + (c << 2)]);
            *(float4*)&h_s[(b << 9) + ((c ^ ((b >> 3) & 7)) << 2)] = v;
        }
        __syncthreads();

        // ---- z[64][32] partial = h @ U_slice over this slab's 64 k ----
        ull acc[8][4];
#pragma unroll
        for (int r = 0; r < 8; r++)
#pragma unroll
            for (int ss = 0; ss < 4; ss++) acc[r][ss] = 0ULL;

#pragma unroll 4
        for (int ci = 0; ci < 16; ci++) {
            int c = cbeg + ci;
            int ph = (c ^ tb) << 2;
            int pu = (c ^ tc) << 2;
            ulonglong2 uv[4];
#pragma unroll
            for (int ss = 0; ss < 4; ss++) uv[ss] = *(const ulonglong2*)&ubase[(ss << 9) + pu];
            // two 4-row halves to bound live registers
#pragma unroll
            for (int hh = 0; hh < 2; hh++) {
                ulonglong2 hv[4];
#pragma unroll
                for (int r = 0; r < 4; r++)
                    hv[r] = *(const ulonglong2*)&hbase[(((hh << 2) + r) << 9) + ph];
#pragma unroll
                for (int r = 0; r < 4; r++)
#pragma unroll
                    for (int ss = 0; ss < 4; ss++) {
                        fma2(acc[(hh << 2) + r][ss], hv[r].x, uv[ss].x);
                        fma2(acc[(hh << 2) + r][ss], hv[r].y, uv[ss].y);
                    }
            }
        }
        __syncthreads();   // h_s reads done; zp aliasing now safe

        // ---- all 8 slabs write partials concurrently (disjoint buffers) ----
#pragma unroll
        for (int r = 0; r < 8; r++)
#pragma unroll
            for (int ss = 0; ss < 4; ss++) {
                float2 f = unpk(acc[r][ss]);
                myzp[(b0 + r) * 33 + c0 + ss] = f.x + f.y;
            }
        __syncthreads();

        // ---- gates + state update (1 element per thread) ----
        {
            int zrow = gb * 33 + u;
            float zi = xzr0, zf = xzr1, zg = xzr2, zo = xzr3;
#pragma unroll
            for (int p = 0; p < 8; p++) {
                const float* zb = zp + p * (64 * 33);
                zi += zb[zrow];
                zf += zb[zrow + 8];
                zg += zb[zrow + 16];
                zo += zb[zrow + 24];
            }
            float iv = 1.0f / (1.0f + expf(-zi));
            float fv = 1.0f / (1.0f + expf(-zf));
            float gv = tanhf(zg);
            float ov = 1.0f / (1.0f + expf(-zo));
            float c_new = fv * c_reg + iv * gv;
            float h_new = ov * tanhf(c_new);
            bool m = mrv != 0u;
            c_reg  = m ? c_new : c_reg;
            h_reg  = m ? h_new : h_reg;
            po_reg = m ? h_new : po_reg;
            h_out[gb * D + cb] = h_reg;
        }

        bool not_last = (s + 1 < T);
        if (not_last) {
            // every thread: release-arrive (orders own h_out store first)
            red_release_add(my_arr, 1u);
        }

        // ---- per-timestep output write (overlaps barrier) ----
        outb[(size_t)(gb * T + t_d) * 1024 + cb] = po_reg;

        if (not_last) {
            if (tid == 0) {
                unsigned tgt_cta = 512u * (unsigned)(s + 1);
                while (ld_acquire(my_arr) < tgt_cta) __nanosleep(64);
                red_release_add(my_cnt, 1u);
                unsigned tgt_all = 64u * (unsigned)(s + 1);
                while (ld_acquire(my_cnt) < tgt_all) __nanosleep(64);
            }
            __syncthreads();
        }
    }

    // final cell state
    g_c[dir * (B * D) + gb * D + cb] = c_reg;
}

// ---------------- final hidden/cell concat ----------------
__global__ void finalize_kernel(float* dout, int out_size) {
    int i = blockIdx.x * blockDim.x + threadIdx.x;
    if (i >= B * 2 * D) return;
    size_t hoff = (size_t)B * T * 1024;
    if ((size_t)out_size < hoff + 2 * (size_t)(B * 2 * D)) return;
    int b = i >> 10, j = i & 1023;
    int dir = j >> 9, u = j & 511;
    int sidx = dir * (B * D) + b * D + u;
    dout[hoff + i] = g_h[0][sidx];   // 256 steps => final ping = 0
    dout[hoff + B * 2 * D + i] = g_c[sidx];
}

// ---------------- host orchestration ----------------
extern "C" void kernel_launch(void* const* d_in, const int* in_sizes, int n_in,
                              void* d_out, int out_size) {
    const float* X   = (const float*)d_in[0];
    const float* Wf1 = (const float*)d_in[1];
    const float* Uf1 = (const float*)d_in[2];
    const float* bf1 = (const float*)d_in[3];
    const float* Wb1 = (const float*)d_in[4];
    const float* Ub1 = (const float*)d_in[5];
    const float* bb1 = (const float*)d_in[6];
    const float* Wf2 = (const float*)d_in[7];
    const float* Uf2 = (const float*)d_in[8];
    const float* bf2 = (const float*)d_in[9];
    const float* Wb2 = (const float*)d_in[10];
    const float* Ub2 = (const float*)d_in[11];
    const float* bb2 = (const float*)d_in[12];
    float* out = (float*)d_out;

    cudaFuncSetAttribute(lstm_scan_kernel,
                         cudaFuncAttributeMaxDynamicSharedMemorySize, SMEM_STEP);

    dim3 ggrid(G4 / 128, M_ROWS / 128);

    // launch order puts scans at positions 4 and 8 (ncu capture slots)
    maskinit_kernel<<<M_ROWS / 4, 128>>>(X);                       // 1
    gemm_bias_kernel<<<ggrid, 256>>>(X, 0, Wf1, bf1, 0, 512);      // 2
    gemm_bias_kernel<<<ggrid, 256>>>(X, 0, Wb1, bb1, 1, 512);      // 3
    lstm_scan_kernel<<<128, 512, SMEM_STEP>>>(Uf1, Ub1, out, 1);   // 4

    gemm_bias_kernel<<<ggrid, 256>>>(nullptr, 1, Wf2, bf2, 0, 1024); // 5
    gemm_bias_kernel<<<ggrid, 256>>>(nullptr, 1, Wb2, bb2, 1, 1024); // 6
    maskinit_kernel<<<M_ROWS / 4, 128>>>(X);                         // 7
    lstm_scan_kernel<<<128, 512, SMEM_STEP>>>(Uf2, Ub2, out, 0);     // 8

    finalize_kernel<<<256, 256>>>(out, out_size);                    // 9
}

// round 12
// speedup vs baseline: 1.7388x; 1.3822x over previous
#include <cuda_runtime.h>
#include <cuda_fp16.h>
#include <math.h>

#define B 64
#define T 256
#define D 512
#define G4 2048
#define M_ROWS (B * T)   // 16384
#define DIN2 1024

typedef unsigned long long ull;

// ---------------- f32x2 helpers (input GEMM kernel) ----------------
__device__ __forceinline__ void fma2(ull &d, ull a, ull b) {
    asm("fma.rn.f32x2 %0, %1, %2, %0;" : "+l"(d) : "l"(a), "l"(b));
}
__device__ __forceinline__ ull dup2(float v) {
    ull r; unsigned u = __float_as_uint(v);
    asm("mov.b64 %0, {%1, %1};" : "=l"(r) : "r"(u));
    return r;
}
__device__ __forceinline__ float2 unpk(ull v) {
    float2 f;
    asm("mov.b64 {%0, %1}, %2;" : "=f"(f.x), "=f"(f.y) : "l"(v));
    return f;
}

// ---------------- release/acquire barrier primitives ----------------
__device__ __forceinline__ void red_release_add(unsigned* p, unsigned v) {
    asm volatile("red.release.gpu.global.add.u32 [%0], %1;"
                 :: "l"(p), "r"(v) : "memory");
}
__device__ __forceinline__ unsigned ld_acquire(const unsigned* p) {
    unsigned v;
    asm volatile("ld.acquire.gpu.global.u32 %0, [%1];"
                 : "=r"(v) : "l"(p) : "memory");
    return v;
}
__device__ __forceinline__ unsigned prmtb(unsigned a, unsigned b, unsigned sel) {
    unsigned r;
    asm("prmt.b32 %0, %1, %2, %3;" : "=r"(r) : "r"(a), "r"(b), "r"(sel));
    return r;
}

// ---------------- warp-MMA primitives (standard PTX; HMMA on sm_103) ----------
__device__ __forceinline__ void ldsm_x4(unsigned* r, unsigned addr) {
    asm volatile("ldmatrix.sync.aligned.m8n8.x4.shared.b16 {%0,%1,%2,%3}, [%4];"
        : "=r"(r[0]), "=r"(r[1]), "=r"(r[2]), "=r"(r[3]) : "r"(addr));
}
__device__ __forceinline__ void ldsm_x2(unsigned* r, unsigned addr) {
    asm volatile("ldmatrix.sync.aligned.m8n8.x2.shared.b16 {%0,%1}, [%2];"
        : "=r"(r[0]), "=r"(r[1]) : "r"(addr));
}
__device__ __forceinline__ void mma16816(float* c, const unsigned* a, const unsigned* b) {
    asm volatile(
        "mma.sync.aligned.m16n8k16.row.col.f32.f16.f16.f32 "
        "{%0,%1,%2,%3}, {%4,%5,%6,%7}, {%8,%9}, {%0,%1,%2,%3};"
        : "+f"(c[0]), "+f"(c[1]), "+f"(c[2]), "+f"(c[3])
        : "r"(a[0]), "r"(a[1]), "r"(a[2]), "r"(a[3]), "r"(b[0]), "r"(b[1]));
}

// ---------------- device scratch ----------------
__device__ float g_xz_f[(size_t)M_ROWS * G4];
__device__ float g_xz_b[(size_t)M_ROWS * G4];
__device__ float g_y1[(size_t)M_ROWS * DIN2];
__device__ unsigned g_hpk[2][2][B * D];     // packed (f16 hi | f16 lo<<16)
__device__ float g_hfin[2 * B * D];
__device__ float g_c[2 * B * D];
__device__ unsigned char g_mask[M_ROWS];
__device__ unsigned g_cta_arr[2][64][32];   // [dir][cta][pad]
__device__ unsigned g_cnt[2][32];           // [dir][pad]

// ---------------- fused: mask + zero packed h + barrier reset ----------------
__global__ void maskinit_kernel(const float* __restrict__ X) {
    int tid = threadIdx.x;
    int gidx = blockIdx.x * 128 + tid;
    if (gidx < 2 * 2 * B * D) ((unsigned*)g_hpk)[gidx] = 0u;
    if (gidx < 2 * 64 * 32) ((unsigned*)g_cta_arr)[gidx] = 0u;
    if (gidx < 2 * 32) ((unsigned*)g_cnt)[gidx] = 0u;
    int row = blockIdx.x * 4 + (tid >> 5);
    int lane = tid & 31;
    const float* p = X + (size_t)row * D;
    int any = 0;
    for (int k = lane; k < D; k += 32) any |= (p[k] != 0.0f);
    any = __any_sync(0xffffffffu, any);
    if (lane == 0) g_mask[row] = (unsigned char)any;
}

// ---------------- GEMM: C[M,2048] = A[M,K] @ W[K,2048] + bias ----------------
__global__ void __launch_bounds__(256, 2) gemm_bias_kernel(
    const float* __restrict__ Aext, int a_is_y1,
    const float* __restrict__ W, const float* __restrict__ bias,
    int c_sel, int K)
{
    const float* A = a_is_y1 ? g_y1 : Aext;
    float* C = c_sel ? g_xz_b : g_xz_f;

    __shared__ float As[2][16 * 128];
    __shared__ float Bs[2][16 * 128];

    int tid = threadIdx.x;
    int m0 = blockIdx.y << 7, n0 = blockIdx.x << 7;
    int warp = tid >> 5, lane = tid & 31;
    int wm = (warp & 3) << 5, wn = (warp >> 2) << 6;
    int lm = (lane >> 3) << 2, ln = (lane & 7) << 2;
    int am = tid & 127, akg = tid >> 7;
    int bn4 = tid & 31, bk0 = tid >> 5;

    ull acc[8][4];
#pragma unroll
    for (int r = 0; r < 8; r++)
#pragma unroll
        for (int s = 0; s < 4; s++) acc[r][s] = 0ULL;

    float4 aR[2], bR[2];
    const size_t arow = (size_t)(m0 + am) * K;

#define LDG_TILE(k0)                                                          \
    aR[0] = *(const float4*)&A[arow + (k0) + (akg << 2)];                     \
    aR[1] = *(const float4*)&A[arow + (k0) + ((akg + 2) << 2)];               \
    bR[0] = *(const float4*)&W[(size_t)((k0) + bk0) * G4 + n0 + (bn4 << 2)];  \
    bR[1] = *(const float4*)&W[(size_t)((k0) + bk0 + 8) * G4 + n0 + (bn4 << 2)];

#define STS_TILE(buf)                                                         \
    {                                                                         \
        float* Ad = As[buf]; float* Bd = Bs[buf];                             \
        Ad[((akg << 2) + 0) * 128 + am] = aR[0].x;                            \
        Ad[((akg << 2) + 1) * 128 + am] = aR[0].y;                            \
        Ad[((akg << 2) + 2) * 128 + am] = aR[0].z;                            \
        Ad[((akg << 2) + 3) * 128 + am] = aR[0].w;                            \
        Ad[(((akg + 2) << 2) + 0) * 128 + am] = aR[1].x;                      \
        Ad[(((akg + 2) << 2) + 1) * 128 + am] = aR[1].y;                      \
        Ad[(((akg + 2) << 2) + 2) * 128 + am] = aR[1].z;                      \
        Ad[(((akg + 2) << 2) + 3) * 128 + am] = aR[1].w;                      \
        *(float4*)&Bd[bk0 * 128 + (bn4 << 2)] = bR[0];                        \
        *(float4*)&Bd[(bk0 + 8) * 128 + (bn4 << 2)] = bR[1];                  \
    }

    LDG_TILE(0);
    STS_TILE(0);
    __syncthreads();

    int KT = K >> 4;
    for (int kt = 0; kt < KT; kt++) {
        int cur = kt & 1;
        if (kt + 1 < KT) { LDG_TILE((kt + 1) << 4); }
        const float* Ab = As[cur];
        const float* Bb = Bs[cur];
#pragma unroll
        for (int kk = 0; kk < 16; kk++) {
            float4 a0 = *(const float4*)&Ab[kk * 128 + wm + lm];
            float4 a1 = *(const float4*)&Ab[kk * 128 + wm + lm + 16];
            ulonglong2 b0 = *(const ulonglong2*)&Bb[kk * 128 + wn + ln];
            ulonglong2 b1 = *(const ulonglong2*)&Bb[kk * 128 + wn + ln + 32];
            ull ap[8];
            ap[0] = dup2(a0.x); ap[1] = dup2(a0.y); ap[2] = dup2(a0.z); ap[3] = dup2(a0.w);
            ap[4] = dup2(a1.x); ap[5] = dup2(a1.y); ap[6] = dup2(a1.z); ap[7] = dup2(a1.w);
#pragma unroll
            for (int r = 0; r < 8; r++) {
                fma2(acc[r][0], ap[r], b0.x);
                fma2(acc[r][1], ap[r], b0.y);
                fma2(acc[r][2], ap[r], b1.x);
                fma2(acc[r][3], ap[r], b1.y);
            }
        }
        if (kt + 1 < KT) {
            STS_TILE(cur ^ 1);
            __syncthreads();
        }
    }

    float4 bias0 = *(const float4*)&bias[n0 + wn + ln];
    float4 bias1 = *(const float4*)&bias[n0 + wn + ln + 32];
#pragma unroll
    for (int r = 0; r < 8; r++) {
        int mrow = m0 + wm + lm + (r < 4 ? r : 12 + r);
        float2 p0 = unpk(acc[r][0]), p1 = unpk(acc[r][1]);
        float2 p2 = unpk(acc[r][2]), p3 = unpk(acc[r][3]);
        float4 v0 = {p0.x + bias0.x, p0.y + bias0.y, p1.x + bias0.z, p1.y + bias0.w};
        float4 v1 = {p2.x + bias1.x, p2.y + bias1.y, p3.x + bias1.z, p3.y + bias1.w};
        size_t crow = (size_t)mrow * G4 + n0 + wn + ln;
        *(float4*)&C[crow] = v0;
        *(float4*)&C[crow + 32] = v1;
    }
#undef LDG_TILE
#undef STS_TILE
}

// ---------------- persistent scan: warp-MMA split-fp16 recurrence ----------------
// 128 CTAs (dir = blk>>6; cta owns 8 units = 32 gate cols), 512 threads (16 warps).
// warp = (m-group 0..3) x (k-slab 0..3). z = h[64,512] @ U[512,32] via
// mma.sync.m16n8k16, 3-term split-f16 (hi*hi + hi*lo + lo*hi), fp32 accum.
#define HSTRIDE_B 1040                       // 520 f16 per row (conflict-free ldmatrix)
#define OFF_HHI  0                           // h hi tile [64][520] f16 = 66560 B
#define OFF_HLO  (64 * HSTRIDE_B)            // h lo tile             = 66560 B
#define OFF_UHI  (2 * 64 * HSTRIDE_B)        // U hi tile [32][520]   = 33280 B
#define OFF_ULO  (OFF_UHI + 32 * HSTRIDE_B)  // U lo tile             = 33280 B
#define OFF_MASK (OFF_ULO + 32 * HSTRIDE_B)  // mask 16 KB
#define SMEM_SCAN (OFF_MASK + 16384)         // 216064 B
// zp[4][64][36] f32 partials (36864 B) alias the h-hi tile after the GEMM phase.

__global__ void __launch_bounds__(512) lstm_scan_kernel(
    const float* __restrict__ Uf, const float* __restrict__ Ub,
    float* dout, int out_is_y1)
{
    extern __shared__ char smb[];
    unsigned smem_base;
    asm("{ .reg .u64 t; cvta.to.shared.u64 t, %1; cvt.u32.u64 %0, t; }"
        : "=r"(smem_base) : "l"(smb));
    unsigned char* mask_s = (unsigned char*)(smb + OFF_MASK);
    float* zp = (float*)(smb + OFF_HHI);

    int tid = threadIdx.x;
    int lane = tid & 31, wid = tid >> 5;
    int dir = blockIdx.x >> 6;
    int cta = blockIdx.x & 63;
    int u0 = cta << 3;

    const float* U = dir ? Ub : Uf;
    const float* xz = dir ? g_xz_b : g_xz_f;
    float* outb = (out_is_y1 ? g_y1 : dout) + dir * D;
    unsigned* my_arr = &g_cta_arr[dir][cta][0];
    unsigned* my_cnt = &g_cnt[dir][0];

    // ---- stage U slice ONCE as hi/lo f16, [n=32][k=512] row-major ----
    for (int i = tid; i < 32 * 512; i += 512) {
        int n = i & 31, k = i >> 5;
        int col = ((n >> 3) << 9) + u0 + (n & 7);
        float v = U[(size_t)k * G4 + col];
        __half hv = __float2half_rn(v);
        __half lv = __float2half_rn(v - __half2float(hv));
        *(__half*)(smb + OFF_UHI + n * HSTRIDE_B + (k << 1)) = hv;
        *(__half*)(smb + OFF_ULO + n * HSTRIDE_B + (k << 1)) = lv;
    }
    // ---- stage full mask ONCE (16KB) ----
    {
        const int4* msrc = (const int4*)g_mask;
        int4* mdst = (int4*)mask_s;
        for (int i = tid; i < M_ROWS / 16; i += 512) mdst[i] = msrc[i];
    }
    __syncthreads();

    // thread roles
    int b = tid >> 3, u = tid & 7;            // gate-phase element (b, unit)
    int cb = u0 + u;
    int mg = wid & 3, ks = wid >> 2;          // MMA: m-group, k-slab
    int arow = (mg << 4) + (lane & 15);
    unsigned a_hi = smem_base + OFF_HHI + arow * HSTRIDE_B + ((lane >> 4) << 4);
    unsigned a_lo = a_hi + (OFF_HLO - OFF_HHI);
    unsigned b_base = smem_base + OFF_UHI + ((lane & 7)) * HSTRIDE_B
                      + (((lane >> 3) & 1) << 4);

    float c_reg = 0.f, h_reg = 0.f, po_reg = 0.f;

    for (int s = 0; s < T; s++) {
        int ping = s & 1;
        int t_d = dir ? (T - 1 - s) : s;
        const unsigned* hsrc = &g_hpk[ping][dir][0];
        unsigned* hdst = &g_hpk[ping ^ 1][dir][0];

        // ---- prefetch xz (long latency, issued first) + mask ----
        int row = b * T + t_d;
        size_t xr = (size_t)row * G4;
        float xz0 = __ldcg(&xz[xr + cb]);
        float xz1 = __ldcg(&xz[xr + 512 + cb]);
        float xz2 = __ldcg(&xz[xr + 1024 + cb]);
        float xz3 = __ldcg(&xz[xr + 1536 + cb]);
        unsigned mrv = mask_s[row];

        // ---- stage packed h -> hi/lo f16 tiles ----
#pragma unroll
        for (int it = 0; it < 16; it++) {
            int idx = tid + (it << 9);        // 0..8191, 4 k-elems each
            int hb = idx >> 7, k0 = (idx & 127) << 2;
            uint4 w = __ldcg((const uint4*)&hsrc[(hb << 9) + k0]);
            unsigned hiA = prmtb(w.x, w.y, 0x5410), hiB = prmtb(w.z, w.w, 0x5410);
            unsigned loA = prmtb(w.x, w.y, 0x7632), loB = prmtb(w.z, w.w, 0x7632);
            unsigned o = hb * HSTRIDE_B + (k0 << 1);
            *(uint2*)(smb + OFF_HHI + o) = make_uint2(hiA, hiB);
            *(uint2*)(smb + OFF_HLO + o) = make_uint2(loA, loB);
        }
        __syncthreads();

        // ---- z partial = h(mg) @ U over k-slab ks, via HMMA ----
        float acc[16];
#pragma unroll
        for (int i = 0; i < 16; i++) acc[i] = 0.f;

#pragma unroll
        for (int kc = 0; kc < 8; kc++) {
            unsigned kbyte = (unsigned)(((ks << 7) + (kc << 4)) << 1);
            unsigned ahi[4], alo[4];
            ldsm_x4(ahi, a_hi + kbyte);
            ldsm_x4(alo, a_lo + kbyte);
#pragma unroll
            for (int nt = 0; nt < 4; nt++) {
                unsigned baddr = b_base + (unsigned)(nt << 3) * HSTRIDE_B + kbyte;
                unsigned bhi[2], blo[2];
                ldsm_x2(bhi, baddr);
                ldsm_x2(blo, baddr + (OFF_ULO - OFF_UHI));
                mma16816(acc + (nt << 2), ahi, bhi);
                mma16816(acc + (nt << 2), ahi, blo);
                mma16816(acc + (nt << 2), alo, bhi);
            }
        }
        __syncthreads();   // all h-tile reads done; zp aliasing now safe

        // ---- write k-slab partials (4 disjoint buffers) ----
        {
            float* myzp = zp + ks * (64 * 36);
            int g = lane >> 2, tt = lane & 3;
#pragma unroll
            for (int nt = 0; nt < 4; nt++) {
                int r0 = (mg << 4) + g, ccol = (nt << 3) + (tt << 1);
                myzp[r0 * 36 + ccol]           = acc[(nt << 2) + 0];
                myzp[r0 * 36 + ccol + 1]       = acc[(nt << 2) + 1];
                myzp[(r0 + 8) * 36 + ccol]     = acc[(nt << 2) + 2];
                myzp[(r0 + 8) * 36 + ccol + 1] = acc[(nt << 2) + 3];
            }
        }
        __syncthreads();

        // ---- gates + state update (1 element per thread) ----
        {
            float zi = xz0, zf = xz1, zg = xz2, zo = xz3;
#pragma unroll
            for (int p = 0; p < 4; p++) {
                const float* zb = zp + p * (64 * 36) + b * 36;
                zi += zb[u];
                zf += zb[8 + u];
                zg += zb[16 + u];
                zo += zb[24 + u];
            }
            float iv = 1.0f / (1.0f + expf(-zi));
            float fv = 1.0f / (1.0f + expf(-zf));
            float gv = tanhf(zg);
            float ov = 1.0f / (1.0f + expf(-zo));
            float c_new = fv * c_reg + iv * gv;
            float h_new = ov * tanhf(c_new);
            bool m = mrv != 0u;
            c_reg  = m ? c_new : c_reg;
            h_reg  = m ? h_new : h_reg;
            po_reg = m ? h_new : po_reg;
            __half hh = __float2half_rn(h_reg);
            __half hl = __float2half_rn(h_reg - __half2float(hh));
            unsigned pk = (unsigned)__half_as_ushort(hh) |
                          ((unsigned)__half_as_ushort(hl) << 16);
            hdst[(b << 9) + cb] = pk;
        }

        bool not_last = (s + 1 < T);
        if (not_last) {
            // every thread: release-arrive (orders own h store first)
            red_release_add(my_arr, 1u);
        }

        // ---- per-timestep output write (overlaps barrier) ----
        outb[(size_t)row * 1024 + cb] = po_reg;

        if (not_last) {
            if (tid == 0) {
                unsigned tgt_cta = 512u * (unsigned)(s + 1);
                while (ld_acquire(my_arr) < tgt_cta) __nanosleep(64);
                red_release_add(my_cnt, 1u);
                unsigned tgt_all = 64u * (unsigned)(s + 1);
                while (ld_acquire(my_cnt) < tgt_all) __nanosleep(64);
            }
            __syncthreads();
        }
    }

    // final hidden + cell state
    g_hfin[dir * (B * D) + b * D + cb] = h_reg;
    g_c[dir * (B * D) + b * D + cb] = c_reg;
}

// ---------------- final hidden/cell concat ----------------
__global__ void finalize_kernel(float* dout, int out_size) {
    int i = blockIdx.x * blockDim.x + threadIdx.x;
    if (i >= B * 2 * D) return;
    size_t hoff = (size_t)B * T * 1024;
    if ((size_t)out_size < hoff + 2 * (size_t)(B * 2 * D)) return;
    int b = i >> 10, j = i & 1023;
    int dir = j >> 9, u = j & 511;
    int sidx = dir * (B * D) + b * D + u;
    dout[hoff + i] = g_hfin[sidx];
    dout[hoff + B * 2 * D + i] = g_c[sidx];
}

// ---------------- host orchestration ----------------
extern "C" void kernel_launch(void* const* d_in, const int* in_sizes, int n_in,
                              void* d_out, int out_size) {
    const float* X   = (const float*)d_in[0];
    const float* Wf1 = (const float*)d_in[1];
    const float* Uf1 = (const float*)d_in[2];
    const float* bf1 = (const float*)d_in[3];
    const float* Wb1 = (const float*)d_in[4];
    const float* Ub1 = (const float*)d_in[5];
    const float* bb1 = (const float*)d_in[6];
    const float* Wf2 = (const float*)d_in[7];
    const float* Uf2 = (const float*)d_in[8];
    const float* bf2 = (const float*)d_in[9];
    const float* Wb2 = (const float*)d_in[10];
    const float* Ub2 = (const float*)d_in[11];
    const float* bb2 = (const float*)d_in[12];
    float* out = (float*)d_out;

    cudaFuncSetAttribute(lstm_scan_kernel,
                         cudaFuncAttributeMaxDynamicSharedMemorySize, SMEM_SCAN);

    dim3 ggrid(G4 / 128, M_ROWS / 128);

    // launch order puts scans at positions 4 and 8 (ncu capture slots)
    maskinit_kernel<<<M_ROWS / 4, 128>>>(X);                       // 1
    gemm_bias_kernel<<<ggrid, 256>>>(X, 0, Wf1, bf1, 0, 512);      // 2
    gemm_bias_kernel<<<ggrid, 256>>>(X, 0, Wb1, bb1, 1, 512);      // 3
    lstm_scan_kernel<<<128, 512, SMEM_SCAN>>>(Uf1, Ub1, out, 1);   // 4

    gemm_bias_kernel<<<ggrid, 256>>>(nullptr, 1, Wf2, bf2, 0, 1024); // 5
    gemm_bias_kernel<<<ggrid, 256>>>(nullptr, 1, Wb2, bb2, 1, 1024); // 6
    maskinit_kernel<<<M_ROWS / 4, 128>>>(X);                         // 7
    lstm_scan_kernel<<<128, 512, SMEM_SCAN>>>(Uf2, Ub2, out, 0);     // 8

    finalize_kernel<<<256, 256>>>(out, out_size);                    // 9
}